// round 4
// baseline (speedup 1.0000x reference)
#include <cuda_runtime.h>
#include <cstdint>

#define BB 8192      // batch rows
#define NN 4096      // feature dim
#define PADF 68      // smem row pitch in floats (16B-aligned, conflict-free)

// 128 MB scratch for the intermediate (B, 4096) tensor.
__device__ float g_scratch[(size_t)BB * NN];

__device__ __forceinline__ uint32_t f2tf32(float f) {
    uint32_t r;
    asm("cvt.rna.tf32.f32 %0, %1;" : "=r"(r) : "f"(f));
    return r;
}

__device__ __forceinline__ void mma16n8k8(float* d, const uint32_t* a,
                                          uint32_t b0, uint32_t b1) {
    asm volatile(
        "mma.sync.aligned.m16n8k8.row.col.f32.tf32.tf32.f32 "
        "{%0,%1,%2,%3}, {%4,%5,%6,%7}, {%8,%9}, {%0,%1,%2,%3};"
        : "+f"(d[0]), "+f"(d[1]), "+f"(d[2]), "+f"(d[3])
        : "r"(a[0]), "r"(a[1]), "r"(a[2]), "r"(a[3]), "r"(b0), "r"(b1));
}

// ---------------------------------------------------------------------------
// Stage 1 (unchanged from R3): one CTA = 128 rows x one 64x64 block (j).
//   C[(m0+row)*4096 + j*64 + q] = sum_p A[(m0+row)*4096 + j*64 + p] * W[j,q,p]
// ---------------------------------------------------------------------------
__global__ __launch_bounds__(128) void gemm_mma(const float* __restrict__ A,
                                                const float* __restrict__ W,
                                                float* __restrict__ C) {
    extern __shared__ __align__(16) uint32_t sm[];
    uint32_t* As = sm;                 // 128 * 68
    uint32_t* Ws = sm + 128 * PADF;    //  64 * 68

    const int tid  = threadIdx.x;
    const int warp = tid >> 5;
    const int lane = tid & 31;
    const int g    = lane >> 2;
    const int t    = lane & 3;
    const int m0   = blockIdx.x * 128;
    const int j    = blockIdx.y;

    {
        const float* Ag = A + (size_t)m0 * NN + j * 64;
#pragma unroll
        for (int i = 0; i < 16; i++) {
            const int g4  = tid + i * 128;
            const int row = g4 >> 4;
            const int c4  = (g4 & 15) * 4;
            const float4 v = *(const float4*)(Ag + (size_t)row * NN + c4);
            uint32_t* d = As + row * PADF + c4;
            d[0] = f2tf32(v.x); d[1] = f2tf32(v.y);
            d[2] = f2tf32(v.z); d[3] = f2tf32(v.w);
        }
    }
    {
        const float* Wg = W + (size_t)j * 4096;
#pragma unroll
        for (int i = 0; i < 8; i++) {
            const int g4 = tid + i * 128;
            const int q  = g4 >> 4;
            const int c4 = (g4 & 15) * 4;
            const float4 v = *(const float4*)(Wg + q * 64 + c4);
            uint32_t* d = Ws + q * PADF + c4;
            d[0] = f2tf32(v.x); d[1] = f2tf32(v.y);
            d[2] = f2tf32(v.z); d[3] = f2tf32(v.w);
        }
    }
    __syncthreads();

    float acc[2][8][4] = {};
    const int rb0 = warp * 32;
#pragma unroll
    for (int ks = 0; ks < 8; ks++) {
        const int k0 = ks * 8;
        uint32_t a[2][4];
#pragma unroll
        for (int mi = 0; mi < 2; mi++) {
            const int rb = rb0 + mi * 16;
            a[mi][0] = As[(rb + g)     * PADF + k0 + t];
            a[mi][1] = As[(rb + g + 8) * PADF + k0 + t];
            a[mi][2] = As[(rb + g)     * PADF + k0 + t + 4];
            a[mi][3] = As[(rb + g + 8) * PADF + k0 + t + 4];
        }
#pragma unroll
        for (int ni = 0; ni < 8; ni++) {
            const uint32_t b0 = Ws[(ni * 8 + g) * PADF + k0 + t];
            const uint32_t b1 = Ws[(ni * 8 + g) * PADF + k0 + t + 4];
            mma16n8k8(acc[0][ni], a[0], b0, b1);
            mma16n8k8(acc[1][ni], a[1], b0, b1);
        }
    }

    float* Cg = C + (size_t)m0 * NN + j * 64;
#pragma unroll
    for (int mi = 0; mi < 2; mi++) {
        const int r0 = rb0 + mi * 16 + g;
#pragma unroll
        for (int ni = 0; ni < 8; ni++) {
            const int col = ni * 8 + t * 2;
            *(float2*)(Cg + (size_t)r0 * NN + col) =
                make_float2(acc[mi][ni][0], acc[mi][ni][1]);
            *(float2*)(Cg + (size_t)(r0 + 8) * NN + col) =
                make_float2(acc[mi][ni][2], acc[mi][ni][3]);
        }
    }
}

// ---------------------------------------------------------------------------
// Stage 2 fused: input permutation + GEMM + output permutation.
//   perm[b, l*64+r]  = out1[b, r*64+l]        (read fused, 8-l groups)
//   out2[b, l, s]    = sum_r perm[b,l,r] * w2[l,s,r]
//   out[b, s*64+l]   = out2[b, l, s]          (write fused via smem staging)
// CTA: 32 rows x 8 l-blocks. 512 threads = 16 warps; warp = (lw, row-half).
// Smem: As[8][32*68], Ws[8][64*68]; epilogue reuses As as st[32][520].
// ---------------------------------------------------------------------------
#define S2_ROWS 32
#define S2_G    8
#define S2_APITCH (S2_ROWS * PADF)       // 2176 words per l-region
#define S2_WPITCH (64 * PADF)            // 4352 words per l-region
#define S2_EPIT 520                      // epilogue row pitch (words)

__global__ __launch_bounds__(512) void gemm_s2_fused(const float* __restrict__ A,
                                                     const float* __restrict__ W,
                                                     float* __restrict__ out) {
    extern __shared__ __align__(16) uint32_t sm[];
    uint32_t* As = sm;                         // 8 * 2176 = 17408 words
    uint32_t* Ws = sm + S2_G * S2_APITCH;      // 8 * 4352 = 34816 words

    const int tid  = threadIdx.x;
    const int warp = tid >> 5;
    const int lane = tid & 31;
    const int g    = lane >> 2;
    const int t    = lane & 3;
    const int m0   = blockIdx.x * S2_ROWS;
    const int l0   = blockIdx.y * S2_G;

    // ---- load A: perm tile, coalesced 32B-chunk reads, tf32 convert ----
    // element (b, r, dl) from A[(m0+b)*4096 + r*64 + l0 + dl]
#pragma unroll
    for (int i = 0; i < 8; i++) {
        const int g4  = tid + i * 512;         // 0..4095
        const int b   = g4 >> 7;               // 0..31
        const int rem = g4 & 127;
        const int r   = rem >> 1;              // 0..63
        const int h   = rem & 1;               // float4 half of 8-chunk
        const float4 v = *(const float4*)(A + (size_t)(m0 + b) * NN + r * 64 + l0 + h * 4);
        uint32_t* d = As + (h * 4) * S2_APITCH + b * PADF + r;
        d[0 * S2_APITCH] = f2tf32(v.x);
        d[1 * S2_APITCH] = f2tf32(v.y);
        d[2 * S2_APITCH] = f2tf32(v.z);
        d[3 * S2_APITCH] = f2tf32(v.w);
    }
    // ---- load W: w2[l, s, r] for l in group ----
#pragma unroll
    for (int i = 0; i < 16; i++) {
        const int g4 = tid + i * 512;          // 0..8191
        const int ls = g4 >> 4;                // l*64 + s
        const int l  = ls >> 6;
        const int s  = ls & 63;
        const int c4 = (g4 & 15) * 4;
        const float4 v = *(const float4*)(W + (size_t)(l0 + l) * 4096 + s * 64 + c4);
        uint32_t* d = Ws + l * S2_WPITCH + s * PADF + c4;
        d[0] = f2tf32(v.x); d[1] = f2tf32(v.y);
        d[2] = f2tf32(v.z); d[3] = f2tf32(v.w);
    }
    __syncthreads();

    // ---- main loop: warp = (lw, rh); warp tile 16(M) x 64(N) ----
    const int lw = warp >> 1;                  // l-block in group (0..7)
    const int rh = warp & 1;                   // row half (0..1)
    const uint32_t* Aw = As + lw * S2_APITCH + (rh * 16) * PADF;
    const uint32_t* Ww = Ws + lw * S2_WPITCH;

    float acc[8][4] = {};
#pragma unroll
    for (int ks = 0; ks < 8; ks++) {
        const int k0 = ks * 8;
        uint32_t a[4];
        a[0] = Aw[(g)     * PADF + k0 + t];
        a[1] = Aw[(g + 8) * PADF + k0 + t];
        a[2] = Aw[(g)     * PADF + k0 + t + 4];
        a[3] = Aw[(g + 8) * PADF + k0 + t + 4];
#pragma unroll
        for (int ni = 0; ni < 8; ni++) {
            const uint32_t b0 = Ww[(ni * 8 + g) * PADF + k0 + t];
            const uint32_t b1 = Ww[(ni * 8 + g) * PADF + k0 + t + 4];
            mma16n8k8(acc[ni], a, b0, b1);
        }
    }
    __syncthreads();   // done reading As/Ws; reuse As as epilogue staging

    // ---- epilogue: stage to st[b][s + 64*dl], then coalesced permuted write ----
    float* st = (float*)As;                    // 32 * 520 = 16640 words <= 17408
    {
        const int r0 = rh * 16 + g;
#pragma unroll
        for (int ni = 0; ni < 8; ni++) {
            const int s = ni * 8 + t * 2;
            *(float2*)(st + r0 * S2_EPIT + s + 64 * lw) =
                make_float2(acc[ni][0], acc[ni][1]);
            *(float2*)(st + (r0 + 8) * S2_EPIT + s + 64 * lw) =
                make_float2(acc[ni][2], acc[ni][3]);
        }
    }
    __syncthreads();
    // out[(m0+b)*4096 + s*64 + l0 + dl] = st[b][s + 64*dl]
#pragma unroll
    for (int i = 0; i < 8; i++) {
        const int g4  = tid + i * 512;         // 0..4095
        const int b   = g4 >> 7;
        const int rem = g4 & 127;
        const int s   = rem >> 1;
        const int h   = rem & 1;
        const float* p = st + b * S2_EPIT + s + 64 * (h * 4);
        float4 v = make_float4(p[0], p[64], p[128], p[192]);
        *(float4*)(out + (size_t)(m0 + b) * NN + s * 64 + l0 + h * 4) = v;
    }
}

extern "C" void kernel_launch(void* const* d_in, const int* in_sizes, int n_in,
                              void* d_out, int out_size) {
    const float* x  = (const float*)d_in[0];   // (8192, 4096)
    const float* w1 = (const float*)d_in[1];   // (64, 64, 64)
    const float* w2 = (const float*)d_in[2];   // (64, 64, 64)
    float* out = (float*)d_out;

    float* scratch = nullptr;
    cudaGetSymbolAddress((void**)&scratch, g_scratch);

    const int smem1 = (128 * PADF + 64 * PADF) * 4;                    // 52224
    const int smem2 = (S2_G * S2_APITCH + S2_G * S2_WPITCH) * 4;       // 208896
    cudaFuncSetAttribute(gemm_mma, cudaFuncAttributeMaxDynamicSharedMemorySize, smem1);
    cudaFuncSetAttribute(gemm_s2_fused, cudaFuncAttributeMaxDynamicSharedMemorySize, smem2);

    // Stage 1: natural-layout block GEMM
    dim3 g1(BB / 128, 64);
    gemm_mma<<<g1, 128, smem1>>>(x, w1, scratch);

    // Stage 2: fused permute -> GEMM -> permuted write
    dim3 g2(BB / S2_ROWS, 64 / S2_G);          // (256, 8)
    gemm_s2_fused<<<g2, 512, smem2>>>(scratch, w2, out);
}